// round 10
// baseline (speedup 1.0000x reference)
#include <cuda_runtime.h>
#include <math.h>

#define BATCH 64
#define TSTEPS 512
#define UNITS 1024
#define FIN 128
#define NCLS 16
#define NCTA 128
#define NTHR 256
#define KA 1152   /* 1024 (h0) + 128 (x) */
#define KB 2048   /* 1024 (o0) + 1024 (h1) */
#define KT 112    /* K tile */

// ------------- static device scratch (no allocations allowed) -------------
__device__ __align__(16) float d_Wa[NCTA * KA * 32];   // 18.9 MB
__device__ __align__(16) float d_Wb[NCTA * KB * 32];   // 33.5 MB
__device__ float d_b0r[4096];
__device__ float d_b1r[4096];
__device__ __align__(16) float d_h0[2][UNITS * BATCH]; // [u][b] double buffered
__device__ __align__(16) float d_h1[2][UNITS * BATCH];
__device__ __align__(16) float d_c0[UNITS * BATCH];
__device__ __align__(16) float d_c1[UNITS * BATCH];
__device__ float d_sum0[BATCH * NCTA];  // [b][cta]
__device__ float d_ssq0[BATCH * NCTA];
__device__ float d_sum1[BATCH * NCTA];
__device__ float d_ssq1[BATCH * NCTA];
__device__ __align__(16) float d_xT[2][FIN * BATCH];   // x_t transposed [f][b]
__device__ unsigned d_cnt;
__device__ unsigned d_gen;

// ------------------------------ prep kernel ------------------------------
// Reorders weights into [cta][k][col] with col = unit_local*4 + gate,
// zeroes state, stages x_0 transposed, resets barrier counters.
__global__ void prep_kernel(const float* __restrict__ in,
                            const float* __restrict__ W0, const float* __restrict__ U0,
                            const float* __restrict__ b0,
                            const float* __restrict__ W1, const float* __restrict__ U1,
                            const float* __restrict__ b1) {
    const long long N0 = (long long)NCTA * KA * 32;            // 4718592
    const long long N1 = (long long)NCTA * KB * 32;            // 8388608
    const long long O2 = N0 + N1;                              // biases
    const long long O3 = O2 + 8192;                            // zero region (4*65536)
    const long long O4 = O3 + 262144;                          // xT (8192)
    const long long TOTAL = O4 + 8192 + 1;
    for (long long idx = (long long)blockIdx.x * blockDim.x + threadIdx.x;
         idx < TOTAL; idx += (long long)gridDim.x * blockDim.x) {
        if (idx < N0) {
            int cta = (int)(idx / (KA * 32));
            int r   = (int)(idx % (KA * 32));
            int k = r >> 5, col = r & 31;
            int gc = (col & 3) * 1024 + cta * 8 + (col >> 2);
            d_Wa[idx] = (k < 1024) ? U0[(long long)k * 4096 + gc]
                                   : W0[(long long)(k - 1024) * 4096 + gc];
        } else if (idx < O2) {
            long long j = idx - N0;
            int cta = (int)(j / (KB * 32));
            int r   = (int)(j % (KB * 32));
            int k = r >> 5, col = r & 31;
            int gc = (col & 3) * 1024 + cta * 8 + (col >> 2);
            d_Wb[j] = (k < 1024) ? W1[(long long)k * 4096 + gc]
                                 : U1[(long long)(k - 1024) * 4096 + gc];
        } else if (idx < O2 + 4096) {
            int j = (int)(idx - O2);
            int gc = ((j & 31) & 3) * 1024 + (j >> 5) * 8 + ((j & 31) >> 2);
            d_b0r[j] = b0[gc];
        } else if (idx < O2 + 8192) {
            int j = (int)(idx - O2 - 4096);
            int gc = ((j & 31) & 3) * 1024 + (j >> 5) * 8 + ((j & 31) >> 2);
            d_b1r[j] = b1[gc];
        } else if (idx < O4) {
            int j = (int)(idx - O3);
            if (j < 65536)        d_c0[j] = 0.f;
            else if (j < 131072)  d_c1[j - 65536] = 0.f;
            else if (j < 196608)  d_h0[0][j - 131072] = 0.f;
            else                  d_h1[0][j - 196608] = 0.f;
        } else if (idx < O4 + 8192) {
            int j = (int)(idx - O4);
            int f = j >> 6, b = j & 63;
            d_xT[0][j] = in[(long long)b * TSTEPS * FIN + f];  // t = 0
        } else {
            d_cnt = 0u;
            d_gen = 0u;
        }
    }
}

// ------------------------------ grid barrier ------------------------------
__device__ __forceinline__ void gridbar(unsigned& genc) {
    __syncthreads();
    if (threadIdx.x == 0) {
        __threadfence();
        unsigned target = ++genc;
        unsigned arr = atomicAdd(&d_cnt, 1u);
        if (arr == NCTA - 1) {
            atomicExch(&d_cnt, 0u);
            __threadfence();
            atomicAdd(&d_gen, 1u);
        } else {
            while (__ldcg(&d_gen) < target) { __nanosleep(64); }
        }
        __threadfence();
    }
    __syncthreads();
}

__device__ __forceinline__ float sigf(float z) { return 1.f / (1.f + expf(-z)); }

// ---------------------------- persistent kernel ----------------------------
__global__ void __launch_bounds__(NTHR, 1)
lstm_persist(const float* __restrict__ in,
             const float* __restrict__ g0, const float* __restrict__ be0,
             const float* __restrict__ g1, const float* __restrict__ be1,
             const float* __restrict__ Wfc, const float* __restrict__ bfc,
             float* __restrict__ out) {
    __shared__ float SA[KT * 64];      // 7168 floats: h-tile / z-exchange / scratch
    __shared__ float SB[KT * 32];      // 3584 floats: w-tile
    __shared__ float SMU[64], SRS[64];

    const int tid = threadIdx.x;
    const int cta = blockIdx.x;
    const int b0i = (tid & 15) * 4;          // 4 batches per thread
    const int c0 = (tid >> 4) * 2, c1 = c0 + 1;  // 2 gate-cols per thread
    unsigned genc = 0;

    for (int t = 0; t < TSTEPS; t++) {
        const int cur = t & 1, nxt = cur ^ 1;

        // ================= Phase A : layer 0 =================
        {
            const float* hsrc = d_h0[cur];
            const float* xsrc = d_xT[cur];
            const float* Wc = d_Wa + (size_t)cta * KA * 32;
            float a00 = 0, a01 = 0, a02 = 0, a03 = 0, a10 = 0, a11 = 0, a12 = 0, a13 = 0;
            for (int k0 = 0; k0 < KA; k0 += KT) {
                const int kk = min(KT, KA - k0);
                for (int i = tid; i < kk * 64; i += NTHR) {
                    int k = k0 + (i >> 6), b = i & 63;
                    SA[i] = (k < 1024) ? __ldcg(&hsrc[k * 64 + b])
                                       : __ldcg(&xsrc[(k - 1024) * 64 + b]);
                }
                for (int i = tid; i < kk * 32; i += NTHR)
                    SB[i] = __ldg(&Wc[(size_t)k0 * 32 + i]);
                __syncthreads();
                #pragma unroll 4
                for (int k = 0; k < kk; k++) {
                    float4 hv = *(const float4*)&SA[(k << 6) + b0i];
                    float w0 = SB[(k << 5) + c0], w1 = SB[(k << 5) + c1];
                    a00 += hv.x * w0; a01 += hv.y * w0; a02 += hv.z * w0; a03 += hv.w * w0;
                    a10 += hv.x * w1; a11 += hv.y * w1; a12 += hv.z * w1; a13 += hv.w * w1;
                }
                __syncthreads();
            }
            const float bb0 = __ldg(&d_b0r[cta * 32 + c0]);
            const float bb1 = __ldg(&d_b0r[cta * 32 + c1]);
            SA[c0 * 64 + b0i + 0] = a00 + bb0; SA[c0 * 64 + b0i + 1] = a01 + bb0;
            SA[c0 * 64 + b0i + 2] = a02 + bb0; SA[c0 * 64 + b0i + 3] = a03 + bb0;
            SA[c1 * 64 + b0i + 0] = a10 + bb1; SA[c1 * 64 + b0i + 1] = a11 + bb1;
            SA[c1 * 64 + b0i + 2] = a12 + bb1; SA[c1 * 64 + b0i + 3] = a13 + bb1;
            __syncthreads();
            for (int e = tid; e < 512; e += NTHR) {
                int ul = e >> 6, b = e & 63;
                float zi = SA[(ul * 4 + 0) * 64 + b];
                float zf = SA[(ul * 4 + 1) * 64 + b];
                float zg = SA[(ul * 4 + 2) * 64 + b];
                float zo = SA[(ul * 4 + 3) * 64 + b];
                int gidx = (cta * 8 + ul) * 64 + b;
                float cn = sigf(zf) * d_c0[gidx] + sigf(zi) * tanhf(zg);
                d_c0[gidx] = cn;
                float hn = sigf(zo) * tanhf(cn);
                __stcg(&d_h0[nxt][gidx], hn);
                SA[2048 + e] = hn;
            }
            __syncthreads();
            if (tid < 64) {
                float s = 0, q = 0;
                #pragma unroll
                for (int u = 0; u < 8; u++) { float v = SA[2048 + u * 64 + tid]; s += v; q += v * v; }
                __stcg(&d_sum0[tid * NCTA + cta], s);
                __stcg(&d_ssq0[tid * NCTA + cta], q);
            }
            if (t + 1 < TSTEPS && tid < 64) {  // stage x_{t+1} transposed: f = cta, b = tid
                __stcg(&d_xT[nxt][cta * 64 + tid],
                       __ldg(&in[(size_t)tid * TSTEPS * FIN + (size_t)(t + 1) * FIN + cta]));
            }
        }
        gridbar(genc);

        // ================= Phase B : layer 1 =================
        if (tid < 64) {
            float s = 0, q = 0;
            for (int i = 0; i < NCTA; i++) {
                s += __ldcg(&d_sum0[tid * NCTA + i]);
                q += __ldcg(&d_ssq0[tid * NCTA + i]);
            }
            float mu = s * (1.f / 1024.f);
            float var = q * (1.f / 1024.f) - mu * mu;
            SMU[tid] = mu; SRS[tid] = rsqrtf(var + 1e-3f);
        }
        __syncthreads();
        {
            const float* hsrc = d_h0[nxt];   // freshly written h0
            const float* h1src = d_h1[cur];
            const float* Wc = d_Wb + (size_t)cta * KB * 32;
            float a00 = 0, a01 = 0, a02 = 0, a03 = 0, a10 = 0, a11 = 0, a12 = 0, a13 = 0;
            for (int k0 = 0; k0 < KB; k0 += KT) {
                const int kk = min(KT, KB - k0);
                for (int i = tid; i < kk * 64; i += NTHR) {
                    int k = k0 + (i >> 6), b = i & 63;
                    float v;
                    if (k < 1024)
                        v = (__ldcg(&hsrc[k * 64 + b]) - SMU[b]) * SRS[b] * __ldg(&g0[k]) + __ldg(&be0[k]);
                    else
                        v = __ldcg(&h1src[(k - 1024) * 64 + b]);
                    SA[i] = v;
                }
                for (int i = tid; i < kk * 32; i += NTHR)
                    SB[i] = __ldg(&Wc[(size_t)k0 * 32 + i]);
                __syncthreads();
                #pragma unroll 4
                for (int k = 0; k < kk; k++) {
                    float4 hv = *(const float4*)&SA[(k << 6) + b0i];
                    float w0 = SB[(k << 5) + c0], w1 = SB[(k << 5) + c1];
                    a00 += hv.x * w0; a01 += hv.y * w0; a02 += hv.z * w0; a03 += hv.w * w0;
                    a10 += hv.x * w1; a11 += hv.y * w1; a12 += hv.z * w1; a13 += hv.w * w1;
                }
                __syncthreads();
            }
            const float bb0 = __ldg(&d_b1r[cta * 32 + c0]);
            const float bb1 = __ldg(&d_b1r[cta * 32 + c1]);
            SA[c0 * 64 + b0i + 0] = a00 + bb0; SA[c0 * 64 + b0i + 1] = a01 + bb0;
            SA[c0 * 64 + b0i + 2] = a02 + bb0; SA[c0 * 64 + b0i + 3] = a03 + bb0;
            SA[c1 * 64 + b0i + 0] = a10 + bb1; SA[c1 * 64 + b0i + 1] = a11 + bb1;
            SA[c1 * 64 + b0i + 2] = a12 + bb1; SA[c1 * 64 + b0i + 3] = a13 + bb1;
            __syncthreads();
            for (int e = tid; e < 512; e += NTHR) {
                int ul = e >> 6, b = e & 63;
                float zi = SA[(ul * 4 + 0) * 64 + b];
                float zf = SA[(ul * 4 + 1) * 64 + b];
                float zg = SA[(ul * 4 + 2) * 64 + b];
                float zo = SA[(ul * 4 + 3) * 64 + b];
                int gidx = (cta * 8 + ul) * 64 + b;
                float cn = sigf(zf) * d_c1[gidx] + sigf(zi) * tanhf(zg);
                d_c1[gidx] = cn;
                float hn = sigf(zo) * tanhf(cn);
                __stcg(&d_h1[nxt][gidx], hn);
                SA[2048 + e] = hn;
            }
            __syncthreads();
            if (tid < 64) {
                float s = 0, q = 0;
                #pragma unroll
                for (int u = 0; u < 8; u++) { float v = SA[2048 + u * 64 + tid]; s += v; q += v * v; }
                __stcg(&d_sum1[tid * NCTA + cta], s);
                __stcg(&d_ssq1[tid * NCTA + cta], q);
            }
        }
        gridbar(genc);

        // ============ Phase C : output (CTAs 0..63, one batch each) ============
        if (cta < 64) {
            const int b = cta;
            if (tid < 128) {
                SA[tid]       = __ldcg(&d_sum1[b * NCTA + tid]);
                SA[128 + tid] = __ldcg(&d_ssq1[b * NCTA + tid]);
            }
            __syncthreads();
            if (tid == 0) {
                float s = 0, q = 0;
                for (int i = 0; i < 128; i++) { s += SA[i]; q += SA[128 + i]; }
                float mu = s * (1.f / 1024.f);
                float var = q * (1.f / 1024.f) - mu * mu;
                SMU[0] = mu; SRS[0] = rsqrtf(var + 1e-3f);
            }
            __syncthreads();
            const float mu = SMU[0], rs = SRS[0];
            for (int u = tid; u < 1024; u += NTHR)
                SA[256 + u] = (__ldcg(&d_h1[nxt][u * 64 + b]) - mu) * rs * __ldg(&g1[u]) + __ldg(&be1[u]);
            __syncthreads();
            {
                const int cls = tid & 15, seg = tid >> 4;
                float p = 0;
                #pragma unroll 8
                for (int u = seg * 64; u < seg * 64 + 64; u++)
                    p += SA[256 + u] * __ldg(&Wfc[u * 16 + cls]);
                SA[1536 + tid] = p;
            }
            __syncthreads();
            if (tid < 16) {
                float z = __ldg(&bfc[tid]);
                #pragma unroll
                for (int s2 = 0; s2 < 16; s2++) z += SA[1536 + s2 * 16 + tid];
                SA[1792 + tid] = z;
            }
            __syncthreads();
            if (tid < 16) {
                float m = -1e30f;
                #pragma unroll
                for (int i = 0; i < 16; i++) m = fmaxf(m, SA[1792 + i]);
                float s = 0;
                #pragma unroll
                for (int i = 0; i < 16; i++) s += expf(SA[1792 + i] - m);
                out[(size_t)b * TSTEPS * NCLS + (size_t)t * NCLS + tid] = expf(SA[1792 + tid] - m) / s;
            }
            __syncthreads();
        }
    }
}

// ------------------------------ launcher ------------------------------
extern "C" void kernel_launch(void* const* d_in, const int* in_sizes, int n_in,
                              void* d_out, int out_size) {
    const float* in  = (const float*)d_in[0];
    const float* W0  = (const float*)d_in[1];
    const float* U0  = (const float*)d_in[2];
    const float* b0  = (const float*)d_in[3];
    const float* g0  = (const float*)d_in[4];
    const float* be0 = (const float*)d_in[5];
    const float* W1  = (const float*)d_in[6];
    const float* U1  = (const float*)d_in[7];
    const float* b1  = (const float*)d_in[8];
    const float* g1  = (const float*)d_in[9];
    const float* be1 = (const float*)d_in[10];
    const float* Wfc = (const float*)d_in[11];
    const float* bfc = (const float*)d_in[12];
    float* out = (float*)d_out;

    prep_kernel<<<8192, 256>>>(in, W0, U0, b0, W1, U1, b1);
    lstm_persist<<<NCTA, NTHR>>>(in, g0, be0, g1, be1, Wfc, bfc, out);
}

// round 12
// speedup vs baseline: 2.5947x; 2.5947x over previous
#include <cuda_runtime.h>
#include <math.h>

#define BATCH 64
#define TSTEPS 512
#define UNITS 1024
#define FIN 128
#define NCLS 16
#define NCTA 128
#define NTHR 512
#define KA 1152   /* 1024 (h0) + 128 (x) */
#define KB 2048   /* 1024 (o0) + 1024 (h1) */

typedef unsigned long long ull;

// ------------- static device scratch (no allocations allowed) -------------
__device__ __align__(16) float d_Wa[NCTA * KA * 32];   // 18.9 MB reordered [U0;W0]
__device__ __align__(16) float d_Wb[NCTA * KB * 32];   // 33.5 MB reordered [W1;U1]
__device__ float d_b0r[4096];
__device__ float d_b1r[4096];
__device__ __align__(16) float d_h0[2][UNITS * BATCH]; // [u][b] double buffered
__device__ __align__(16) float d_h1[2][UNITS * BATCH];
__device__ __align__(16) float d_c0[UNITS * BATCH];
__device__ __align__(16) float d_c1[UNITS * BATCH];
__device__ float d_sum0[BATCH * NCTA];  // [b][cta]
__device__ float d_ssq0[BATCH * NCTA];
__device__ float d_sum1[BATCH * NCTA];
__device__ float d_ssq1[BATCH * NCTA];
__device__ __align__(16) float d_xT[2][FIN * BATCH];   // x_t transposed [f][b]
__device__ unsigned d_cnt;
__device__ unsigned d_gen;

// ------------------------------ prep kernel ------------------------------
__global__ void prep_kernel(const float* __restrict__ in,
                            const float* __restrict__ W0, const float* __restrict__ U0,
                            const float* __restrict__ b0,
                            const float* __restrict__ W1, const float* __restrict__ U1,
                            const float* __restrict__ b1) {
    const long long N0 = (long long)NCTA * KA * 32;
    const long long N1 = (long long)NCTA * KB * 32;
    const long long O2 = N0 + N1;
    const long long O3 = O2 + 8192;
    const long long O4 = O3 + 262144;
    const long long TOTAL = O4 + 8192 + 1;
    for (long long idx = (long long)blockIdx.x * blockDim.x + threadIdx.x;
         idx < TOTAL; idx += (long long)gridDim.x * blockDim.x) {
        if (idx < N0) {
            int cta = (int)(idx / (KA * 32));
            int r   = (int)(idx % (KA * 32));
            int k = r >> 5, col = r & 31;
            int gc = (col & 3) * 1024 + cta * 8 + (col >> 2);
            d_Wa[idx] = (k < 1024) ? U0[(long long)k * 4096 + gc]
                                   : W0[(long long)(k - 1024) * 4096 + gc];
        } else if (idx < O2) {
            long long j = idx - N0;
            int cta = (int)(j / (KB * 32));
            int r   = (int)(j % (KB * 32));
            int k = r >> 5, col = r & 31;
            int gc = (col & 3) * 1024 + cta * 8 + (col >> 2);
            d_Wb[j] = (k < 1024) ? W1[(long long)k * 4096 + gc]
                                 : U1[(long long)(k - 1024) * 4096 + gc];
        } else if (idx < O2 + 4096) {
            int j = (int)(idx - O2);
            int gc = ((j & 31) & 3) * 1024 + (j >> 5) * 8 + ((j & 31) >> 2);
            d_b0r[j] = b0[gc];
        } else if (idx < O2 + 8192) {
            int j = (int)(idx - O2 - 4096);
            int gc = ((j & 31) & 3) * 1024 + (j >> 5) * 8 + ((j & 31) >> 2);
            d_b1r[j] = b1[gc];
        } else if (idx < O4) {
            int j = (int)(idx - O3);
            if (j < 65536)        d_c0[j] = 0.f;
            else if (j < 131072)  d_c1[j - 65536] = 0.f;
            else if (j < 196608)  d_h0[0][j - 131072] = 0.f;
            else                  d_h1[0][j - 196608] = 0.f;
        } else if (idx < O4 + 8192) {
            int j = (int)(idx - O4);
            int f = j >> 6, b = j & 63;
            d_xT[0][j] = in[(long long)b * TSTEPS * FIN + f];  // t = 0
        } else {
            d_cnt = 0u;
            d_gen = 0u;
        }
    }
}

// ------------------------------ grid barrier ------------------------------
__device__ __forceinline__ void gridbar(unsigned& genc) {
    __syncthreads();
    if (threadIdx.x == 0) {
        __threadfence();
        unsigned target = ++genc;
        unsigned arr = atomicAdd(&d_cnt, 1u);
        if (arr == NCTA - 1) {
            atomicExch(&d_cnt, 0u);
            __threadfence();
            atomicAdd(&d_gen, 1u);
        } else {
            while (__ldcg(&d_gen) < target) { __nanosleep(64); }
        }
        __threadfence();
    }
    __syncthreads();
}

__device__ __forceinline__ float sigf(float z) { return 1.f / (1.f + expf(-z)); }

// ------------------------------ f32x2 helpers ------------------------------
__device__ __forceinline__ void ffma2(ull& d, ull a, ull b) {
    asm("fma.rn.f32x2 %0, %1, %2, %0;" : "+l"(d) : "l"(a), "l"(b));
}
__device__ __forceinline__ ull splat2(float w) {
    ull r; asm("mov.b64 %0, {%1, %1};" : "=l"(r) : "f"(w)); return r;
}
__device__ __forceinline__ ull addf2(ull a, ull b) {
    ull r; asm("add.rn.f32x2 %0, %1, %2;" : "=l"(r) : "l"(a), "l"(b)); return r;
}
__device__ __forceinline__ float2 unpk(ull v) {
    float2 f; asm("mov.b64 {%0, %1}, %2;" : "=f"(f.x), "=f"(f.y) : "l"(v)); return f;
}

// ---------------------- tiled GEMM, 4-way K-split ----------------------
// PH=0: K=1152, src = h0 (k<1024) else xT.  PH=1: K=2048, src = LN(h0) (k<1024) else h1.
// Result z+bias left in smemf[8192 .. 10240) as [col][64].
template<int PH>
__device__ __forceinline__ void gemm_block(
    float* __restrict__ smemf,
    const float4* __restrict__ srcA, const float4* __restrict__ srcB,
    const float* __restrict__ Wc, const float* __restrict__ brow,
    const float* __restrict__ gam, const float* __restrict__ bet,
    const float* __restrict__ smu, const float* __restrict__ srs, int tid)
{
    const int sp = tid >> 7, stid = tid & 127;
    const int cg = stid & 15, bg = stid >> 4;
    const int c0 = cg * 2, b0 = bg * 8;
    const int KSP = (PH == 0) ? 288 : 512;
    const int NT  = (PH == 0) ? 9 : 16;
    float* HT = smemf + sp * 2048;
    float* WT = smemf + 8192 + sp * 1024;
    ull A0[4] = {0ull,0ull,0ull,0ull}, A1[4] = {0ull,0ull,0ull,0ull};

    for (int tt = 0; tt < NT; tt++) {
        const int kb = sp * KSP + tt * 32;
        #pragma unroll
        for (int jj = 0; jj < 4; jj++) {
            int j = stid + jj * 128;
            int k = j >> 4, q = j & 15;
            int gk = kb + k;
            float4 v;
            if (PH == 0) {
                v = (gk < 1024) ? __ldcg(&srcA[gk * 16 + q])
                                : __ldcg(&srcB[(gk - 1024) * 16 + q]);
            } else {
                if (gk < 1024) {
                    v = __ldcg(&srcA[gk * 16 + q]);
                    float4 m4 = *(const float4*)&smu[q * 4];
                    float4 r4 = *(const float4*)&srs[q * 4];
                    float gg = __ldg(&gam[gk]), bb = __ldg(&bet[gk]);
                    v.x = (v.x - m4.x) * r4.x * gg + bb;
                    v.y = (v.y - m4.y) * r4.y * gg + bb;
                    v.z = (v.z - m4.z) * r4.z * gg + bb;
                    v.w = (v.w - m4.w) * r4.w * gg + bb;
                } else {
                    v = __ldcg(&srcB[(gk - 1024) * 16 + q]);
                }
            }
            *(float4*)&HT[k * 64 + q * 4] = v;
        }
        #pragma unroll
        for (int jj = 0; jj < 2; jj++) {
            int j = stid + jj * 128;
            *(float4*)&WT[j * 4] = __ldg((const float4*)&Wc[(size_t)kb * 32 + j * 4]);
        }
        __syncthreads();
        #pragma unroll 8
        for (int k = 0; k < 32; k++) {
            ulonglong2 p = *(ulonglong2*)&HT[k * 64 + b0];
            ulonglong2 r = *(ulonglong2*)&HT[k * 64 + b0 + 4];
            float2 wv = *(float2*)&WT[k * 32 + c0];
            ull w0 = splat2(wv.x), w1 = splat2(wv.y);
            ffma2(A0[0], p.x, w0); ffma2(A0[1], p.y, w0);
            ffma2(A0[2], r.x, w0); ffma2(A0[3], r.y, w0);
            ffma2(A1[0], p.x, w1); ffma2(A1[1], p.y, w1);
            ffma2(A1[2], r.x, w1); ffma2(A1[3], r.y, w1);
        }
        __syncthreads();
    }
    // deterministic cross-span reduction (spans 1-3 -> smem, span 0 adds in order)
    if (sp > 0) {
        ull* row = (ull*)smemf + (size_t)(sp - 1) * 1280 + (size_t)stid * 10;
        *(ulonglong2*)&row[0] = make_ulonglong2(A0[0], A0[1]);
        *(ulonglong2*)&row[2] = make_ulonglong2(A0[2], A0[3]);
        *(ulonglong2*)&row[4] = make_ulonglong2(A1[0], A1[1]);
        *(ulonglong2*)&row[6] = make_ulonglong2(A1[2], A1[3]);
    }
    __syncthreads();
    if (sp == 0) {
        #pragma unroll
        for (int s = 1; s < 4; s++) {
            ull* row = (ull*)smemf + (size_t)(s - 1) * 1280 + (size_t)stid * 10;
            ulonglong2 u0 = *(ulonglong2*)&row[0];
            ulonglong2 u1 = *(ulonglong2*)&row[2];
            ulonglong2 u2 = *(ulonglong2*)&row[4];
            ulonglong2 u3 = *(ulonglong2*)&row[6];
            A0[0] = addf2(A0[0], u0.x); A0[1] = addf2(A0[1], u0.y);
            A0[2] = addf2(A0[2], u1.x); A0[3] = addf2(A0[3], u1.y);
            A1[0] = addf2(A1[0], u2.x); A1[1] = addf2(A1[1], u2.y);
            A1[2] = addf2(A1[2], u3.x); A1[3] = addf2(A1[3], u3.y);
        }
        float* Z = smemf + 8192;
        float bb0 = __ldg(&brow[c0]), bb1 = __ldg(&brow[c0 + 1]);
        #pragma unroll
        for (int j = 0; j < 4; j++) {
            float2 v0 = unpk(A0[j]);
            Z[c0 * 64 + b0 + 2 * j]     = v0.x + bb0;
            Z[c0 * 64 + b0 + 2 * j + 1] = v0.y + bb0;
            float2 v1 = unpk(A1[j]);
            Z[(c0 + 1) * 64 + b0 + 2 * j]     = v1.x + bb1;
            Z[(c0 + 1) * 64 + b0 + 2 * j + 1] = v1.y + bb1;
        }
    }
    __syncthreads();
}

// ---------------------------- persistent kernel ----------------------------
extern __shared__ float smemf[];   // 12288 floats = 48 KB dynamic

__global__ void __launch_bounds__(NTHR, 1)
lstm_persist(const float* __restrict__ in,
             const float* __restrict__ g0, const float* __restrict__ be0,
             const float* __restrict__ g1, const float* __restrict__ be1,
             const float* __restrict__ Wfc, const float* __restrict__ bfc,
             float* __restrict__ out) {
    __shared__ float SMU[64], SRS[64];
    __shared__ float PS[4][64], PQ[4][64];
    __shared__ float LR[256];
    __shared__ float LG[16];

    const int tid = threadIdx.x;
    const int cta = blockIdx.x;
    unsigned genc = 0;
    float* Z  = smemf + 8192;   // [32 col][64 b]
    float* HN = smemf + 10240;  // [8 u][64 b]

    for (int t = 0; t < TSTEPS; t++) {
        const int cur = t & 1, nxt = cur ^ 1;

        // ================= Phase A : layer 0 =================
        gemm_block<0>(smemf, (const float4*)d_h0[cur], (const float4*)d_xT[cur],
                      d_Wa + (size_t)cta * KA * 32, d_b0r + cta * 32,
                      0, 0, 0, 0, tid);
        {
            int ul = tid >> 6, b = tid & 63;
            float zi = Z[(ul * 4 + 0) * 64 + b];
            float zf = Z[(ul * 4 + 1) * 64 + b];
            float zg = Z[(ul * 4 + 2) * 64 + b];
            float zo = Z[(ul * 4 + 3) * 64 + b];
            int gidx = (cta * 8 + ul) * 64 + b;
            float cn = sigf(zf) * d_c0[gidx] + sigf(zi) * tanhf(zg);
            d_c0[gidx] = cn;
            float hn = sigf(zo) * tanhf(cn);
            __stcg(&d_h0[nxt][gidx], hn);
            HN[tid] = hn;
        }
        __syncthreads();
        if (tid < 64) {
            float s = 0, q = 0;
            #pragma unroll
            for (int u = 0; u < 8; u++) { float v = HN[u * 64 + tid]; s += v; q += v * v; }
            __stcg(&d_sum0[tid * NCTA + cta], s);
            __stcg(&d_ssq0[tid * NCTA + cta], q);
        }
        if (t + 1 < TSTEPS && tid < 64) {
            __stcg(&d_xT[nxt][cta * 64 + tid],
                   __ldg(&in[(size_t)tid * TSTEPS * FIN + (size_t)(t + 1) * FIN + cta]));
        }
        gridbar(genc);

        // ================= LN0 stats =================
        if (tid < 256) {
            int b = tid >> 2, p = tid & 3;
            float s = 0, q = 0;
            for (int i = p * 32; i < p * 32 + 32; i++) {
                s += __ldcg(&d_sum0[b * NCTA + i]);
                q += __ldcg(&d_ssq0[b * NCTA + i]);
            }
            PS[p][b] = s; PQ[p][b] = q;
        }
        __syncthreads();
        if (tid < 64) {
            float s = PS[0][tid] + PS[1][tid] + PS[2][tid] + PS[3][tid];
            float q = PQ[0][tid] + PQ[1][tid] + PQ[2][tid] + PQ[3][tid];
            float mu = s * (1.f / 1024.f);
            float var = q * (1.f / 1024.f) - mu * mu;
            SMU[tid] = mu; SRS[tid] = rsqrtf(var + 1e-3f);
        }
        __syncthreads();

        // ================= Phase B : layer 1 =================
        gemm_block<1>(smemf, (const float4*)d_h0[nxt], (const float4*)d_h1[cur],
                      d_Wb + (size_t)cta * KB * 32, d_b1r + cta * 32,
                      g0, be0, SMU, SRS, tid);
        {
            int ul = tid >> 6, b = tid & 63;
            float zi = Z[(ul * 4 + 0) * 64 + b];
            float zf = Z[(ul * 4 + 1) * 64 + b];
            float zg = Z[(ul * 4 + 2) * 64 + b];
            float zo = Z[(ul * 4 + 3) * 64 + b];
            int gidx = (cta * 8 + ul) * 64 + b;
            float cn = sigf(zf) * d_c1[gidx] + sigf(zi) * tanhf(zg);
            d_c1[gidx] = cn;
            float hn = sigf(zo) * tanhf(cn);
            __stcg(&d_h1[nxt][gidx], hn);
            HN[tid] = hn;
        }
        __syncthreads();
        if (tid < 64) {
            float s = 0, q = 0;
            #pragma unroll
            for (int u = 0; u < 8; u++) { float v = HN[u * 64 + tid]; s += v; q += v * v; }
            __stcg(&d_sum1[tid * NCTA + cta], s);
            __stcg(&d_ssq1[tid * NCTA + cta], q);
        }
        gridbar(genc);

        // ============ Phase C : output (CTAs 0..63, one batch each) ============
        if (cta < 64) {
            const int b = cta;
            if (tid < 128) {
                LR[tid]       = __ldcg(&d_sum1[b * NCTA + tid]);
                LR[128 + tid] = __ldcg(&d_ssq1[b * NCTA + tid]);
            }
            __syncthreads();
            if (tid < 32) {
                float s = LR[tid] + LR[tid + 32] + LR[tid + 64] + LR[tid + 96];
                float q = LR[128 + tid] + LR[160 + tid] + LR[192 + tid] + LR[224 + tid];
                #pragma unroll
                for (int o = 16; o; o >>= 1) {
                    s += __shfl_xor_sync(0xffffffffu, s, o);
                    q += __shfl_xor_sync(0xffffffffu, q, o);
                }
                if (tid == 0) {
                    float mu = s * (1.f / 1024.f);
                    float var = q * (1.f / 1024.f) - mu * mu;
                    SMU[0] = mu; SRS[0] = rsqrtf(var + 1e-3f);
                }
            }
            __syncthreads();
            const float mu = SMU[0], rs = SRS[0];
            float* ON = smemf;          // 1024
            float* FC = smemf + 1024;   // 512
            for (int u = tid; u < 1024; u += NTHR)
                ON[u] = (__ldcg(&d_h1[nxt][u * 64 + b]) - mu) * rs * __ldg(&g1[u]) + __ldg(&be1[u]);
            __syncthreads();
            {
                const int cls = tid & 15, seg = tid >> 4;   // 32 segs x 32 units
                float p = 0.f;
                #pragma unroll 8
                for (int u = seg * 32; u < seg * 32 + 32; u++)
                    p += ON[u] * __ldg(&Wfc[u * 16 + cls]);
                FC[seg * 16 + cls] = p;
            }
            __syncthreads();
            if (tid < 16) {
                float z = __ldg(&bfc[tid]);
                #pragma unroll
                for (int s2 = 0; s2 < 32; s2++) z += FC[s2 * 16 + tid];
                LG[tid] = z;
            }
            __syncthreads();
            if (tid < 16) {
                float m = -1e30f;
                #pragma unroll
                for (int i = 0; i < 16; i++) m = fmaxf(m, LG[i]);
                float s = 0.f;
                #pragma unroll
                for (int i = 0; i < 16; i++) s += expf(LG[i] - m);
                out[(size_t)b * TSTEPS * NCLS + (size_t)t * NCLS + tid] = expf(LG[tid] - m) / s;
            }
            __syncthreads();
        }
    }
}

// ------------------------------ launcher ------------------------------
extern "C" void kernel_launch(void* const* d_in, const int* in_sizes, int n_in,
                              void* d_out, int out_size) {
    const float* in  = (const float*)d_in[0];
    const float* W0  = (const float*)d_in[1];
    const float* U0  = (const float*)d_in[2];
    const float* b0  = (const float*)d_in[3];
    const float* g0  = (const float*)d_in[4];
    const float* be0 = (const float*)d_in[5];
    const float* W1  = (const float*)d_in[6];
    const float* U1  = (const float*)d_in[7];
    const float* b1  = (const float*)d_in[8];
    const float* g1  = (const float*)d_in[9];
    const float* be1 = (const float*)d_in[10];
    const float* Wfc = (const float*)d_in[11];
    const float* bfc = (const float*)d_in[12];
    float* out = (float*)d_out;

    // Static __shared__ (~3.6 KB) + 48 KB dynamic exceeds the default 48 KB
    // per-block limit; opt in to a larger dynamic-smem ceiling. Host-side
    // attribute set: not a stream op, graph-capture safe, deterministic.
    static int smem_attr_set = 0;
    if (!smem_attr_set) {
        cudaFuncSetAttribute(lstm_persist, cudaFuncAttributeMaxDynamicSharedMemorySize, 65536);
        smem_attr_set = 1;
    }

    prep_kernel<<<8192, 256>>>(in, W0, U0, b0, W1, U1, b1);
    lstm_persist<<<NCTA, NTHR, 49152>>>(in, g0, be0, g1, be1, Wfc, bfc, out);
}

// round 13
// speedup vs baseline: 2.7664x; 1.0662x over previous
#include <cuda_runtime.h>
#include <math.h>

#define BATCH 64
#define TSTEPS 512
#define UNITS 1024
#define FIN 128
#define NCLS 16
#define NCTA 128
#define NTHR 512
#define KA 1152   /* 1024 (h0) + 128 (x) */
#define KB 2048   /* 1024 (o0) + 1024 (h1) */

typedef unsigned long long ull;

// ------------- static device scratch (no allocations allowed) -------------
__device__ __align__(16) float d_Wa[NCTA * KA * 32];   // reordered [U0;W0]
__device__ __align__(16) float d_Wb[NCTA * KB * 32];   // reordered [W1*g0;U1]
__device__ float d_b0r[4096];
__device__ float d_b1r[4096];   // b1 + sum_k W1[k,c]*be0[k]
__device__ float d_cs[4096];    // sum_k (W1*g0)[k,c]
__device__ __align__(16) float d_h0[2][UNITS * BATCH]; // [u][b] double buffered
__device__ __align__(16) float d_h1[2][UNITS * BATCH];
__device__ __align__(16) float d_c0[UNITS * BATCH];
__device__ __align__(16) float d_c1[UNITS * BATCH];
__device__ float d_sum0[BATCH * NCTA];  // [b][cta]
__device__ float d_ssq0[BATCH * NCTA];
__device__ float d_sum1[BATCH * NCTA];
__device__ float d_ssq1[BATCH * NCTA];
__device__ __align__(16) float d_xT[2][FIN * BATCH];   // x_t transposed [f][b]
__device__ unsigned d_cnt;
__device__ unsigned d_gen;

// ------------------------------ prep kernel ------------------------------
__global__ void prep_kernel(const float* __restrict__ in,
                            const float* __restrict__ W0, const float* __restrict__ U0,
                            const float* __restrict__ b0,
                            const float* __restrict__ W1, const float* __restrict__ U1,
                            const float* __restrict__ b1,
                            const float* __restrict__ g0, const float* __restrict__ be0) {
    const long long N0 = (long long)NCTA * KA * 32;
    const long long N1 = (long long)NCTA * KB * 32;
    const long long O2 = N0 + N1;
    const long long O3 = O2 + 8192;
    const long long O4 = O3 + 262144;
    const long long TOTAL = O4 + 8192 + 1;
    for (long long idx = (long long)blockIdx.x * blockDim.x + threadIdx.x;
         idx < TOTAL; idx += (long long)gridDim.x * blockDim.x) {
        if (idx < N0) {
            int cta = (int)(idx / (KA * 32));
            int r   = (int)(idx % (KA * 32));
            int k = r >> 5, col = r & 31;
            int gc = (col & 3) * 1024 + cta * 8 + (col >> 2);
            d_Wa[idx] = (k < 1024) ? U0[(long long)k * 4096 + gc]
                                   : W0[(long long)(k - 1024) * 4096 + gc];
        } else if (idx < O2) {
            long long j = idx - N0;
            int cta = (int)(j / (KB * 32));
            int r   = (int)(j % (KB * 32));
            int k = r >> 5, col = r & 31;
            int gc = (col & 3) * 1024 + cta * 8 + (col >> 2);
            d_Wb[j] = (k < 1024) ? W1[(long long)k * 4096 + gc] * g0[k]
                                 : U1[(long long)(k - 1024) * 4096 + gc];
        } else if (idx < O2 + 4096) {
            int j = (int)(idx - O2);
            int gc = ((j & 31) & 3) * 1024 + (j >> 5) * 8 + ((j & 31) >> 2);
            d_b0r[j] = b0[gc];
        } else if (idx < O2 + 8192) {
            // fold LN0 beta term into bias; compute colsum of scaled weights
            int j = (int)(idx - O2 - 4096);
            int gc = ((j & 31) & 3) * 1024 + (j >> 5) * 8 + ((j & 31) >> 2);
            float sbe = 0.f, sg = 0.f;
            for (int k = 0; k < 1024; k++) {
                float w = W1[(long long)k * 4096 + gc];
                sbe += w * be0[k];
                sg  += w * g0[k];
            }
            d_b1r[j] = b1[gc] + sbe;
            d_cs[j]  = sg;
        } else if (idx < O4) {
            int j = (int)(idx - O3);
            if (j < 65536)        d_c0[j] = 0.f;
            else if (j < 131072)  d_c1[j - 65536] = 0.f;
            else if (j < 196608)  d_h0[0][j - 131072] = 0.f;
            else                  d_h1[0][j - 196608] = 0.f;
        } else if (idx < O4 + 8192) {
            int j = (int)(idx - O4);
            int f = j >> 6, b = j & 63;
            d_xT[0][j] = in[(long long)b * TSTEPS * FIN + f];  // t = 0
        } else {
            d_cnt = 0u;
            d_gen = 0u;
        }
    }
}

// ------------------------------ grid barrier ------------------------------
__device__ __forceinline__ void gridbar(unsigned& genc) {
    __syncthreads();
    if (threadIdx.x == 0) {
        __threadfence();
        unsigned target = ++genc;
        unsigned arr = atomicAdd(&d_cnt, 1u);
        if (arr == NCTA - 1) {
            atomicExch(&d_cnt, 0u);
            __threadfence();
            atomicAdd(&d_gen, 1u);
        } else {
            while (__ldcg(&d_gen) < target) { __nanosleep(64); }
        }
        __threadfence();
    }
    __syncthreads();
}

__device__ __forceinline__ float sigf(float z) { return 1.f / (1.f + expf(-z)); }

// ------------------------------ f32x2 helpers ------------------------------
__device__ __forceinline__ void ffma2(ull& d, ull a, ull b) {
    asm("fma.rn.f32x2 %0, %1, %2, %0;" : "+l"(d) : "l"(a), "l"(b));
}
__device__ __forceinline__ ull splat2(float w) {
    ull r; asm("mov.b64 %0, {%1, %1};" : "=l"(r) : "f"(w)); return r;
}
__device__ __forceinline__ ull addf2(ull a, ull b) {
    ull r; asm("add.rn.f32x2 %0, %1, %2;" : "=l"(r) : "l"(a), "l"(b)); return r;
}
__device__ __forceinline__ float2 unpk(ull v) {
    float2 f; asm("mov.b64 {%0, %1}, %2;" : "=f"(f.x), "=f"(f.y) : "l"(v)); return f;
}
__device__ __forceinline__ void cpa16(void* dst, const void* src) {
    unsigned d = (unsigned)__cvta_generic_to_shared(dst);
    asm volatile("cp.async.cg.shared.global [%0], [%1], 16;" :: "r"(d), "l"(src));
}
__device__ __forceinline__ void cpa_commit() {
    asm volatile("cp.async.commit_group;");
}
__device__ __forceinline__ void cpa_wait1() {
    asm volatile("cp.async.wait_group 1;");
}

// ---------------------- pipelined tiled GEMM, 4-way K-split ----------------
// PH=0: K=1152, src=[h0;xT], epilogue z = A + bias.
// PH=1: K=2048, src=[h0 raw; h1]; spans 0-1 accumulate the LN-scaled part,
//        spans 2-3 the plain part; epilogue z = rs_b*As + Ap - m2_b*cs + bias.
// Result z left in smemf[36864 .. 38912) as [col][64].
// Span buffers: smemf + sp*9216, 3 buffers of 3072 floats (2048 h + 1024 w).
template<int PH>
__device__ __forceinline__ void gemm_block(
    float* __restrict__ smemf,
    const float4* __restrict__ srcA, const float4* __restrict__ srcB,
    const float* __restrict__ Wc, const float* __restrict__ brow,
    const float* __restrict__ csum,
    const float* __restrict__ srs, const float* __restrict__ sm2, int tid)
{
    const int sp = tid >> 7, stid = tid & 127;
    const int cg = stid & 15, bg = stid >> 4;
    const int c0 = cg * 2, b0 = bg * 8;
    const int KSP = (PH == 0) ? 288 : 512;
    const int NT  = (PH == 0) ? 9 : 16;
    float* BUF = smemf + sp * 9216;
    ull A0[4] = {0ull,0ull,0ull,0ull}, A1[4] = {0ull,0ull,0ull,0ull};

    auto stage = [&](int ttp) {
        if (ttp < NT) {
            float* H = BUF + (ttp % 3) * 3072;
            float* W = H + 2048;
            const int kb = sp * KSP + ttp * 32;
            #pragma unroll
            for (int jj = 0; jj < 4; jj++) {
                int j = stid + jj * 128;
                int k = j >> 4, q = j & 15;
                int gk = kb + k;
                const float4* s = (gk < 1024) ? (srcA + gk * 16 + q)
                                              : (srcB + (gk - 1024) * 16 + q);
                cpa16(&H[k * 64 + q * 4], s);
            }
            #pragma unroll
            for (int jj = 0; jj < 2; jj++) {
                int j = stid + jj * 128;
                cpa16(&W[j * 4], &Wc[(size_t)kb * 32 + j * 4]);
            }
        }
        cpa_commit();
    };

    stage(0);
    stage(1);
    #pragma unroll 1
    for (int tt = 0; tt < NT; tt++) {
        cpa_wait1();
        __syncthreads();
        const float* H = BUF + (tt % 3) * 3072;
        const float* W = H + 2048;
        #pragma unroll 8
        for (int k = 0; k < 32; k++) {
            ulonglong2 p = *(const ulonglong2*)&H[k * 64 + b0];
            ulonglong2 r = *(const ulonglong2*)&H[k * 64 + b0 + 4];
            float2 wv = *(const float2*)&W[k * 32 + c0];
            ull w0 = splat2(wv.x), w1 = splat2(wv.y);
            ffma2(A0[0], p.x, w0); ffma2(A0[1], p.y, w0);
            ffma2(A0[2], r.x, w0); ffma2(A0[3], r.y, w0);
            ffma2(A1[0], p.x, w1); ffma2(A1[1], p.y, w1);
            ffma2(A1[2], r.x, w1); ffma2(A1[3], r.y, w1);
        }
        stage(tt + 2);
    }
    __syncthreads();   // all compute done before reusing span0/1 buffers for reduction

    // cross-span exchange: spans 1-3 dump partials to smem rows
    if (sp > 0) {
        ull* row = (ull*)smemf + (size_t)(sp - 1) * 1280 + (size_t)stid * 10;
        *(ulonglong2*)&row[0] = make_ulonglong2(A0[0], A0[1]);
        *(ulonglong2*)&row[2] = make_ulonglong2(A0[2], A0[3]);
        *(ulonglong2*)&row[4] = make_ulonglong2(A1[0], A1[1]);
        *(ulonglong2*)&row[6] = make_ulonglong2(A1[2], A1[3]);
    }
    __syncthreads();
    if (sp == 0) {
        float* Z = smemf + 36864;
        float bb0 = __ldg(&brow[c0]), bb1 = __ldg(&brow[c0 + 1]);
        if (PH == 0) {
            #pragma unroll
            for (int s = 1; s < 4; s++) {
                ull* row = (ull*)smemf + (size_t)(s - 1) * 1280 + (size_t)stid * 10;
                ulonglong2 u0 = *(ulonglong2*)&row[0];
                ulonglong2 u1 = *(ulonglong2*)&row[2];
                ulonglong2 u2 = *(ulonglong2*)&row[4];
                ulonglong2 u3 = *(ulonglong2*)&row[6];
                A0[0] = addf2(A0[0], u0.x); A0[1] = addf2(A0[1], u0.y);
                A0[2] = addf2(A0[2], u1.x); A0[3] = addf2(A0[3], u1.y);
                A1[0] = addf2(A1[0], u2.x); A1[1] = addf2(A1[1], u2.y);
                A1[2] = addf2(A1[2], u3.x); A1[3] = addf2(A1[3], u3.y);
            }
            #pragma unroll
            for (int j = 0; j < 4; j++) {
                float2 v0 = unpk(A0[j]);
                Z[c0 * 64 + b0 + 2 * j]     = v0.x + bb0;
                Z[c0 * 64 + b0 + 2 * j + 1] = v0.y + bb0;
                float2 v1 = unpk(A1[j]);
                Z[(c0 + 1) * 64 + b0 + 2 * j]     = v1.x + bb1;
                Z[(c0 + 1) * 64 + b0 + 2 * j + 1] = v1.y + bb1;
            }
        } else {
            // scaled part: own (span0) + span1 ; plain part: span2 + span3
            ull* r1 = (ull*)smemf + 0 * 1280 + (size_t)stid * 10;
            ull* r2 = (ull*)smemf + 1 * 1280 + (size_t)stid * 10;
            ull* r3 = (ull*)smemf + 2 * 1280 + (size_t)stid * 10;
            ull As0[4], As1[4], Ap0[4], Ap1[4];
            {
                ulonglong2 u0 = *(ulonglong2*)&r1[0], u1 = *(ulonglong2*)&r1[2];
                ulonglong2 u2 = *(ulonglong2*)&r1[4], u3 = *(ulonglong2*)&r1[6];
                As0[0] = addf2(A0[0], u0.x); As0[1] = addf2(A0[1], u0.y);
                As0[2] = addf2(A0[2], u1.x); As0[3] = addf2(A0[3], u1.y);
                As1[0] = addf2(A1[0], u2.x); As1[1] = addf2(A1[1], u2.y);
                As1[2] = addf2(A1[2], u3.x); As1[3] = addf2(A1[3], u3.y);
            }
            {
                ulonglong2 u0 = *(ulonglong2*)&r2[0], u1 = *(ulonglong2*)&r2[2];
                ulonglong2 u2 = *(ulonglong2*)&r2[4], u3 = *(ulonglong2*)&r2[6];
                ulonglong2 v0 = *(ulonglong2*)&r3[0], v1 = *(ulonglong2*)&r3[2];
                ulonglong2 v2 = *(ulonglong2*)&r3[4], v3 = *(ulonglong2*)&r3[6];
                Ap0[0] = addf2(u0.x, v0.x); Ap0[1] = addf2(u0.y, v0.y);
                Ap0[2] = addf2(u1.x, v1.x); Ap0[3] = addf2(u1.y, v1.y);
                Ap1[0] = addf2(u2.x, v2.x); Ap1[1] = addf2(u2.y, v2.y);
                Ap1[2] = addf2(u3.x, v3.x); Ap1[3] = addf2(u3.y, v3.y);
            }
            float cs0 = __ldg(&csum[c0]), cs1 = __ldg(&csum[c0 + 1]);
            #pragma unroll
            for (int j = 0; j < 4; j++) {
                int b = b0 + 2 * j;
                float r0 = srs[b], rr1 = srs[b + 1];
                float m0 = sm2[b], m1 = sm2[b + 1];
                float2 s0 = unpk(As0[j]), p0 = unpk(Ap0[j]);
                Z[c0 * 64 + b]     = r0  * s0.x + p0.x - m0 * cs0 + bb0;
                Z[c0 * 64 + b + 1] = rr1 * s0.y + p0.y - m1 * cs0 + bb0;
                float2 s1 = unpk(As1[j]), p1 = unpk(Ap1[j]);
                Z[(c0 + 1) * 64 + b]     = r0  * s1.x + p1.x - m0 * cs1 + bb1;
                Z[(c0 + 1) * 64 + b + 1] = rr1 * s1.y + p1.y - m1 * cs1 + bb1;
            }
        }
    }
    __syncthreads();
}

// ---------------------------- persistent kernel ----------------------------
extern __shared__ float smemf[];   // 39424 floats = 157696 B dynamic

__global__ void __launch_bounds__(NTHR, 1)
lstm_persist(const float* __restrict__ in,
             const float* __restrict__ g1, const float* __restrict__ be1,
             const float* __restrict__ Wfc, const float* __restrict__ bfc,
             float* __restrict__ out) {
    __shared__ float SM2[64], SRS[64];      // m2 = mu*rs, rs
    __shared__ float PS[4][64], PQ[4][64];
    __shared__ float LR[256];
    __shared__ float LG[16];
    __shared__ float CMU[2];                // phase C mu/rs

    const int tid = threadIdx.x;
    const int cta = blockIdx.x;
    unsigned genc = 0;
    float* Z  = smemf + 36864;  // [32 col][64 b]
    float* HN = smemf + 38912;  // [8 u][64 b]

    for (int t = 0; t < TSTEPS; t++) {
        const int cur = t & 1, nxt = cur ^ 1;

        // ================= Phase A : layer 0 =================
        gemm_block<0>(smemf, (const float4*)d_h0[cur], (const float4*)d_xT[cur],
                      d_Wa + (size_t)cta * KA * 32, d_b0r + cta * 32,
                      0, 0, 0, tid);
        {
            int ul = tid >> 6, b = tid & 63;
            float zi = Z[(ul * 4 + 0) * 64 + b];
            float zf = Z[(ul * 4 + 1) * 64 + b];
            float zg = Z[(ul * 4 + 2) * 64 + b];
            float zo = Z[(ul * 4 + 3) * 64 + b];
            int gidx = (cta * 8 + ul) * 64 + b;
            float cn = sigf(zf) * d_c0[gidx] + sigf(zi) * tanhf(zg);
            d_c0[gidx] = cn;
            float hn = sigf(zo) * tanhf(cn);
            __stcg(&d_h0[nxt][gidx], hn);
            HN[tid] = hn;
        }
        __syncthreads();
        if (tid < 64) {
            float s = 0, q = 0;
            #pragma unroll
            for (int u = 0; u < 8; u++) { float v = HN[u * 64 + tid]; s += v; q += v * v; }
            __stcg(&d_sum0[tid * NCTA + cta], s);
            __stcg(&d_ssq0[tid * NCTA + cta], q);
        }
        if (t + 1 < TSTEPS && tid < 64) {
            __stcg(&d_xT[nxt][cta * 64 + tid],
                   __ldg(&in[(size_t)tid * TSTEPS * FIN + (size_t)(t + 1) * FIN + cta]));
        }
        gridbar(genc);

        // ================= LN0 stats (redundant per CTA) =================
        if (tid < 256) {
            int b = tid >> 2, p = tid & 3;
            float s = 0, q = 0;
            for (int i = p * 32; i < p * 32 + 32; i++) {
                s += __ldcg(&d_sum0[b * NCTA + i]);
                q += __ldcg(&d_ssq0[b * NCTA + i]);
            }
            PS[p][b] = s; PQ[p][b] = q;
        }
        __syncthreads();
        if (tid < 64) {
            float s = PS[0][tid] + PS[1][tid] + PS[2][tid] + PS[3][tid];
            float q = PQ[0][tid] + PQ[1][tid] + PQ[2][tid] + PQ[3][tid];
            float mu = s * (1.f / 1024.f);
            float var = q * (1.f / 1024.f) - mu * mu;
            float rs = rsqrtf(var + 1e-3f);
            SRS[tid] = rs; SM2[tid] = mu * rs;
        }
        __syncthreads();

        // ================= Phase B : layer 1 (LN folded into weights) ======
        gemm_block<1>(smemf, (const float4*)d_h0[nxt], (const float4*)d_h1[cur],
                      d_Wb + (size_t)cta * KB * 32, d_b1r + cta * 32,
                      d_cs + cta * 32, SRS, SM2, tid);
        {
            int ul = tid >> 6, b = tid & 63;
            float zi = Z[(ul * 4 + 0) * 64 + b];
            float zf = Z[(ul * 4 + 1) * 64 + b];
            float zg = Z[(ul * 4 + 2) * 64 + b];
            float zo = Z[(ul * 4 + 3) * 64 + b];
            int gidx = (cta * 8 + ul) * 64 + b;
            float cn = sigf(zf) * d_c1[gidx] + sigf(zi) * tanhf(zg);
            d_c1[gidx] = cn;
            float hn = sigf(zo) * tanhf(cn);
            __stcg(&d_h1[nxt][gidx], hn);
            HN[tid] = hn;
        }
        __syncthreads();
        if (tid < 64) {
            float s = 0, q = 0;
            #pragma unroll
            for (int u = 0; u < 8; u++) { float v = HN[u * 64 + tid]; s += v; q += v * v; }
            __stcg(&d_sum1[tid * NCTA + cta], s);
            __stcg(&d_ssq1[tid * NCTA + cta], q);
        }
        gridbar(genc);

        // ============ Phase C : output (CTAs 0..63, one batch each) ============
        if (cta < 64) {
            const int b = cta;
            if (tid < 128) {
                LR[tid]       = __ldcg(&d_sum1[b * NCTA + tid]);
                LR[128 + tid] = __ldcg(&d_ssq1[b * NCTA + tid]);
            }
            __syncthreads();
            if (tid < 32) {
                float s = LR[tid] + LR[tid + 32] + LR[tid + 64] + LR[tid + 96];
                float q = LR[128 + tid] + LR[160 + tid] + LR[192 + tid] + LR[224 + tid];
                #pragma unroll
                for (int o = 16; o; o >>= 1) {
                    s += __shfl_xor_sync(0xffffffffu, s, o);
                    q += __shfl_xor_sync(0xffffffffu, q, o);
                }
                if (tid == 0) {
                    float mu = s * (1.f / 1024.f);
                    float var = q * (1.f / 1024.f) - mu * mu;
                    CMU[0] = mu; CMU[1] = rsqrtf(var + 1e-3f);
                }
            }
            __syncthreads();
            const float mu = CMU[0], rs = CMU[1];
            float* ON = smemf;          // 1024
            float* FC = smemf + 1024;   // 512
            for (int u = tid; u < 1024; u += NTHR)
                ON[u] = (__ldcg(&d_h1[nxt][u * 64 + b]) - mu) * rs * __ldg(&g1[u]) + __ldg(&be1[u]);
            __syncthreads();
            {
                const int cls = tid & 15, seg = tid >> 4;   // 32 segs x 32 units
                float p = 0.f;
                #pragma unroll 8
                for (int u = seg * 32; u < seg * 32 + 32; u++)
                    p += ON[u] * __ldg(&Wfc[u * 16 + cls]);
                FC[seg * 16 + cls] = p;
            }
            __syncthreads();
            if (tid < 16) {
                float z = __ldg(&bfc[tid]);
                #pragma unroll
                for (int s2 = 0; s2 < 32; s2++) z += FC[s2 * 16 + tid];
                LG[tid] = z;
            }
            __syncthreads();
            if (tid < 16) {
                float m = -1e30f;
                #pragma unroll
                for (int i = 0; i < 16; i++) m = fmaxf(m, LG[i]);
                float s = 0.f;
                #pragma unroll
                for (int i = 0; i < 16; i++) s += expf(LG[i] - m);
                out[(size_t)b * TSTEPS * NCLS + (size_t)t * NCLS + tid] = expf(LG[tid] - m) / s;
            }
            __syncthreads();
        }
    }
}

// ------------------------------ launcher ------------------------------
extern "C" void kernel_launch(void* const* d_in, const int* in_sizes, int n_in,
                              void* d_out, int out_size) {
    const float* in  = (const float*)d_in[0];
    const float* W0  = (const float*)d_in[1];
    const float* U0  = (const float*)d_in[2];
    const float* b0  = (const float*)d_in[3];
    const float* g0  = (const float*)d_in[4];
    const float* be0 = (const float*)d_in[5];
    const float* W1  = (const float*)d_in[6];
    const float* U1  = (const float*)d_in[7];
    const float* b1  = (const float*)d_in[8];
    const float* g1  = (const float*)d_in[9];
    const float* be1 = (const float*)d_in[10];
    const float* Wfc = (const float*)d_in[11];
    const float* bfc = (const float*)d_in[12];
    float* out = (float*)d_out;

    static int smem_attr_set = 0;
    if (!smem_attr_set) {
        cudaFuncSetAttribute(lstm_persist, cudaFuncAttributeMaxDynamicSharedMemorySize, 157696);
        smem_attr_set = 1;
    }

    prep_kernel<<<8192, 256>>>(in, W0, U0, b0, W1, U1, b1, g0, be0);
    lstm_persist<<<NCTA, NTHR, 157696>>>(in, g1, be1, Wfc, bfc, out);
}